// round 5
// baseline (speedup 1.0000x reference)
#include <cuda_runtime.h>
#include <cuda_bf16.h>
#include <cstdint>

#define NB 4
#define NC 256
#define NHW 4096
#define KT 32
#define SP 40     // bf16 smem row stride (80B)
#define SPB 80    // u8 smem row stride for KT8=64 (64 data + 16 pad)
#define KT8 64    // int8 gemm k-tile (bytes)

// ---------------- scratch ----------------
__device__ __nv_bfloat16 g_hT_hi[NB*NHW*NC];
__device__ __nv_bfloat16 g_hT_lo[NB*NHW*NC];
__device__ __nv_bfloat16 g_w_hi[4*NC*NC];
__device__ __nv_bfloat16 g_w_lo[4*NC*NC];
__device__ uint8_t       g_q[NB*NHW*NC];            // raw q codes [b][n][c] in [0,255]
__device__ uint8_t       g_k[NB*NHW*NC];            // raw k codes [b][m][c]
__device__ uint8_t       g_v[NB*NC*NHW];            // raw v codes [b][c][m]
__device__ int           g_qs[NB*NHW];              // sum_c q codes
__device__ int           g_ks[NB*NHW];              // sum_c k codes
__device__ int           g_vs[NB*NC];               // sum_m v codes
__device__ int           g_as[NB*NHW];              // sum_m attn codes
__device__ float         g_S[(size_t)NB*NHW*NHW];
__device__ uint8_t       g_a[(size_t)NB*NHW*NHW];   // raw attn codes [b][n][m]
__device__ __nv_bfloat16 g_hoT_hi[NB*NHW*NC];
__device__ __nv_bfloat16 g_hoT_lo[NB*NHW*NC];

// ---------------- helpers ----------------
__device__ __forceinline__ void mma16816(float d[4], const uint32_t a[4], const uint32_t b[2]) {
    asm volatile(
        "mma.sync.aligned.m16n8k16.row.col.f32.bf16.bf16.f32 "
        "{%0,%1,%2,%3},{%4,%5,%6,%7},{%8,%9},{%0,%1,%2,%3};\n"
        : "+f"(d[0]), "+f"(d[1]), "+f"(d[2]), "+f"(d[3])
        : "r"(a[0]), "r"(a[1]), "r"(a[2]), "r"(a[3]), "r"(b[0]), "r"(b[1]));
}
__device__ __forceinline__ void mma16832u8(int d[4], const uint32_t a[4], const uint32_t b[2]) {
    asm volatile(
        "mma.sync.aligned.m16n8k32.row.col.s32.u8.u8.s32 "
        "{%0,%1,%2,%3},{%4,%5,%6,%7},{%8,%9},{%0,%1,%2,%3};\n"
        : "+r"(d[0]), "+r"(d[1]), "+r"(d[2]), "+r"(d[3])
        : "r"(a[0]), "r"(a[1]), "r"(a[2]), "r"(a[3]), "r"(b[0]), "r"(b[1]));
}
__device__ __forceinline__ void cp16(void* s, const void* g) {
    uint32_t sa = (uint32_t)__cvta_generic_to_shared(s);
    asm volatile("cp.async.cg.shared.global [%0],[%1],16;\n" :: "r"(sa), "l"(g));
}
#define CP_COMMIT() asm volatile("cp.async.commit_group;\n")
#define CP_WAIT0()  asm volatile("cp.async.wait_group 0;\n")
#define CP_WAIT1()  asm volatile("cp.async.wait_group 1;\n")

__device__ __forceinline__ float fq_raw(float v, float dinv, float zp) {
    // raw clamped code in [0,255]
    float q = rintf(v * dinv) + zp;
    return fminf(fmaxf(q, 0.0f), 255.0f);
}

// ---------------- 1) GroupNorm -> hT hi/lo [b][n][c] ----------------
__global__ void __launch_bounds__(256) gn_kernel(const float* __restrict__ x,
                                                 const float* __restrict__ gam,
                                                 const float* __restrict__ bet) {
    int b = blockIdx.x >> 5, gr = blockIdx.x & 31;
    const float* xp = x + ((size_t)(b * NC) + gr * 8) * NHW;
    int tid = threadIdx.x;
    const int Nf4 = 8 * NHW / 4;
    const float4* x4 = (const float4*)xp;
    float s = 0.f, ss = 0.f;
    for (int i = tid; i < Nf4; i += 256) {
        float4 v = x4[i];
        s  += v.x + v.y + v.z + v.w;
        ss += v.x * v.x + v.y * v.y + v.z * v.z + v.w * v.w;
    }
    __shared__ float rs[8], rss[8], s_sc[8], s_sh[8];
    #pragma unroll
    for (int o = 16; o; o >>= 1) {
        s  += __shfl_down_sync(0xffffffffu, s, o);
        ss += __shfl_down_sync(0xffffffffu, ss, o);
    }
    if ((tid & 31) == 0) { rs[tid >> 5] = s; rss[tid >> 5] = ss; }
    __syncthreads();
    float ts = 0.f, tss = 0.f;
    #pragma unroll
    for (int k = 0; k < 8; k++) { ts += rs[k]; tss += rss[k]; }
    const float inv = 1.0f / (float)(8 * NHW);
    float mu = ts * inv;
    float var = tss * inv - mu * mu;
    float rstd = 1.0f / sqrtf(var + 1e-6f);
    if (tid < 8) {
        float gm = gam[gr * 8 + tid];
        s_sc[tid] = gm * rstd;
        s_sh[tid] = bet[gr * 8 + tid] - mu * gm * rstd;
    }
    __syncthreads();
    __nv_bfloat16* Hh = g_hT_hi + (size_t)b * NHW * NC + gr * 8;
    __nv_bfloat16* Hl = g_hT_lo + (size_t)b * NHW * NC + gr * 8;
    for (int n = tid; n < NHW; n += 256) {
        union { __nv_bfloat16 h[8]; uint4 u; } ph, pl;
        #pragma unroll
        for (int c = 0; c < 8; c++) {
            float v = xp[(size_t)c * NHW + n] * s_sc[c] + s_sh[c];
            __nv_bfloat16 hi = __float2bfloat16(v);
            ph.h[c] = hi;
            pl.h[c] = __float2bfloat16(v - __bfloat162float(hi));
        }
        *(uint4*)&Hh[(size_t)n * NC] = ph.u;
        *(uint4*)&Hl[(size_t)n * NC] = pl.u;
    }
}

// ---------------- 2) weight split ----------------
__global__ void __launch_bounds__(256) wsplit_kernel(const float* __restrict__ wq,
                                                     const float* __restrict__ wk,
                                                     const float* __restrict__ wv,
                                                     const float* __restrict__ wp) {
    int idx = blockIdx.x * 256 + threadIdx.x;
    const float* ws[4] = {wq, wk, wv, wp};
    #pragma unroll
    for (int m = 0; m < 4; m++) {
        float v = ws[m][idx];
        __nv_bfloat16 hi = __float2bfloat16(v);
        g_w_hi[m * NC * NC + idx] = hi;
        g_w_lo[m * NC * NC + idx] = __float2bfloat16(v - __bfloat162float(hi));
    }
}

// ---------------- 3) QKV: split-bf16 mma conv -> u8 codes ----------------
__global__ void __launch_bounds__(256) qkv_kernel(
    const float* __restrict__ bq, const float* __restrict__ bk, const float* __restrict__ bv,
    const float* __restrict__ dqp, const float* __restrict__ zqp,
    const float* __restrict__ dkp, const float* __restrict__ zkp,
    const float* __restrict__ dvp, const float* __restrict__ zvp) {
    int z = blockIdx.z;
    int b = z / 3, which = z - b * 3;
    const __nv_bfloat16* Wh = g_w_hi + which * NC * NC;
    const __nv_bfloat16* Wl = g_w_lo + which * NC * NC;
    const float* bias;
    float d, zp;
    if (which == 0)      { bias = bq; d = dqp[0]; zp = zqp[0]; }
    else if (which == 1) { bias = bk; d = dkp[0]; zp = zkp[0]; }
    else                 { bias = bv; d = dvp[0]; zp = zvp[0]; }
    int n0 = blockIdx.x * 128, o0 = blockIdx.y * 128;
    const __nv_bfloat16* Ahg = g_hT_hi + (size_t)b * NHW * NC;
    const __nv_bfloat16* Alg = g_hT_lo + (size_t)b * NHW * NC;

    __shared__ union SmU {
        struct { __nv_bfloat16 Ah[128][SP], Al[128][SP], Bh[128][SP], Bl[128][SP]; } m;
        uint8_t tb[128][144];
    } sm;

    int tid = threadIdx.x, warp = tid >> 5, lane = tid & 31;
    int g = lane >> 2, ti = lane & 3, wr = warp & 1, wc = warp >> 1;
    float acc[4][4][4] = {};

    for (int k0 = 0; k0 < NC; k0 += KT) {
        #pragma unroll
        for (int u = 0; u < 2; u++) {
            int c = tid + u * 256; int r = c >> 2, q = (c & 3) * 8;
            cp16(&sm.m.Ah[r][q], &Ahg[(size_t)(n0 + r) * NC + k0 + q]);
            cp16(&sm.m.Al[r][q], &Alg[(size_t)(n0 + r) * NC + k0 + q]);
            cp16(&sm.m.Bh[r][q], &Wh[(o0 + r) * NC + k0 + q]);
            cp16(&sm.m.Bl[r][q], &Wl[(o0 + r) * NC + k0 + q]);
        }
        CP_COMMIT(); CP_WAIT0();
        __syncthreads();
        #pragma unroll
        for (int kk = 0; kk < KT; kk += 16) {
            uint32_t ah[4][4], al[4][4], bh[4][2], bl[4][2];
            #pragma unroll
            for (int mi = 0; mi < 4; mi++) {
                int r = wr * 64 + mi * 16;
                ah[mi][0] = *(const uint32_t*)&sm.m.Ah[r + g    ][kk + 2 * ti];
                ah[mi][1] = *(const uint32_t*)&sm.m.Ah[r + g + 8][kk + 2 * ti];
                ah[mi][2] = *(const uint32_t*)&sm.m.Ah[r + g    ][kk + 2 * ti + 8];
                ah[mi][3] = *(const uint32_t*)&sm.m.Ah[r + g + 8][kk + 2 * ti + 8];
                al[mi][0] = *(const uint32_t*)&sm.m.Al[r + g    ][kk + 2 * ti];
                al[mi][1] = *(const uint32_t*)&sm.m.Al[r + g + 8][kk + 2 * ti];
                al[mi][2] = *(const uint32_t*)&sm.m.Al[r + g    ][kk + 2 * ti + 8];
                al[mi][3] = *(const uint32_t*)&sm.m.Al[r + g + 8][kk + 2 * ti + 8];
            }
            #pragma unroll
            for (int ni = 0; ni < 4; ni++) {
                int c = wc * 32 + ni * 8;
                bh[ni][0] = *(const uint32_t*)&sm.m.Bh[c + g][kk + 2 * ti];
                bh[ni][1] = *(const uint32_t*)&sm.m.Bh[c + g][kk + 2 * ti + 8];
                bl[ni][0] = *(const uint32_t*)&sm.m.Bl[c + g][kk + 2 * ti];
                bl[ni][1] = *(const uint32_t*)&sm.m.Bl[c + g][kk + 2 * ti + 8];
            }
            #pragma unroll
            for (int mi = 0; mi < 4; mi++)
                #pragma unroll
                for (int ni = 0; ni < 4; ni++) {
                    mma16816(acc[mi][ni], ah[mi], bh[ni]);
                    mma16816(acc[mi][ni], ah[mi], bl[ni]);
                    mma16816(acc[mi][ni], al[mi], bh[ni]);
                }
        }
        __syncthreads();
    }

    float dinv = 1.0f / d;
    if (which < 2) {
        uint8_t* Out = (which == 0 ? g_q : g_k) + (size_t)b * NHW * NC;
        #pragma unroll
        for (int mi = 0; mi < 4; mi++) {
            int n = n0 + wr * 64 + mi * 16 + g;
            #pragma unroll
            for (int ni = 0; ni < 4; ni++) {
                int o = o0 + wc * 32 + ni * 8 + 2 * ti;
                float b0 = bias[o], b1 = bias[o + 1];
                union { uint8_t c[2]; uint16_t u; } p0, p1;
                p0.c[0] = (uint8_t)fq_raw(acc[mi][ni][0] + b0, dinv, zp);
                p0.c[1] = (uint8_t)fq_raw(acc[mi][ni][1] + b1, dinv, zp);
                p1.c[0] = (uint8_t)fq_raw(acc[mi][ni][2] + b0, dinv, zp);
                p1.c[1] = (uint8_t)fq_raw(acc[mi][ni][3] + b1, dinv, zp);
                *(uint16_t*)&Out[(size_t)n * NC + o]       = p0.u;
                *(uint16_t*)&Out[(size_t)(n + 8) * NC + o] = p1.u;
            }
        }
    } else {
        #pragma unroll
        for (int mi = 0; mi < 4; mi++) {
            int nl = wr * 64 + mi * 16 + g;
            #pragma unroll
            for (int ni = 0; ni < 4; ni++) {
                int ol = wc * 32 + ni * 8 + 2 * ti;
                float b0 = bias[o0 + ol], b1 = bias[o0 + ol + 1];
                sm.tb[ol    ][nl    ] = (uint8_t)fq_raw(acc[mi][ni][0] + b0, dinv, zp);
                sm.tb[ol + 1][nl    ] = (uint8_t)fq_raw(acc[mi][ni][1] + b1, dinv, zp);
                sm.tb[ol    ][nl + 8] = (uint8_t)fq_raw(acc[mi][ni][2] + b0, dinv, zp);
                sm.tb[ol + 1][nl + 8] = (uint8_t)fq_raw(acc[mi][ni][3] + b1, dinv, zp);
            }
        }
        __syncthreads();
        int r = tid >> 1, half = (tid & 1) * 64;
        #pragma unroll
        for (int j = 0; j < 64; j += 16)
            *(uint4*)&g_v[((size_t)b * NC + o0 + r) * NHW + n0 + half + j] =
                *(uint4*)&sm.tb[r][half + j];
    }
}

// ---------------- 4) row sums of q/k codes (256 each) ----------------
__global__ void __launch_bounds__(256) sums_qk_kernel() {
    int warp = threadIdx.x >> 5, lane = threadIdx.x & 31;
    int row = blockIdx.x * 8 + warp;                 // [0, 2*NB*NHW)
    const uint8_t* src = (row < NB * NHW) ? g_q : g_k;
    int r = (row < NB * NHW) ? row : row - NB * NHW;
    uint2 w = *(const uint2*)&src[(size_t)r * NC + lane * 8];
    unsigned s = __dp4a(w.x, 0x01010101u, 0u);
    s = __dp4a(w.y, 0x01010101u, s);
    #pragma unroll
    for (int o = 16; o; o >>= 1) s += __shfl_down_sync(0xffffffffu, s, o);
    if (lane == 0) {
        if (row < NB * NHW) g_qs[r] = (int)s; else g_ks[r] = (int)s;
    }
}

// ---------------- 5) row sums of v codes (4096 each) ----------------
__global__ void __launch_bounds__(256) vsum_kernel() {
    int warp = threadIdx.x >> 5, lane = threadIdx.x & 31;
    int row = blockIdx.x * 8 + warp;                 // [0, NB*NC)
    const uint8_t* src = g_v + (size_t)row * NHW;
    unsigned s = 0u;
    #pragma unroll
    for (int j = 0; j < 8; j++) {
        uint4 w = *(const uint4*)&src[lane * 16 + j * 512];
        s = __dp4a(w.x, 0x01010101u, s);
        s = __dp4a(w.y, 0x01010101u, s);
        s = __dp4a(w.z, 0x01010101u, s);
        s = __dp4a(w.w, 0x01010101u, s);
    }
    #pragma unroll
    for (int o = 16; o; o >>= 1) s += __shfl_down_sync(0xffffffffu, s, o);
    if (lane == 0) g_vs[row] = (int)s;
}

// ---------------- 6) gemm1: int8 exact, S = scale*(U - zq*ks - zk*qs + C*zq*zk) ----------------
__global__ void __launch_bounds__(256) gemm1_kernel(const float* __restrict__ dqp,
                                                    const float* __restrict__ zqp,
                                                    const float* __restrict__ dkp,
                                                    const float* __restrict__ zkp) {
    int b = blockIdx.z, m0 = blockIdx.x * 128, n0 = blockIdx.y * 128;
    const uint8_t* A  = g_q + (size_t)b * NHW * NC;
    const uint8_t* Bm = g_k + (size_t)b * NHW * NC;
    __shared__ uint8_t As[2][128][SPB], Bs[2][128][SPB];
    int tid = threadIdx.x, warp = tid >> 5, lane = tid & 31;
    int g = lane >> 2, ti = lane & 3, wr = warp & 1, wc = warp >> 1;
    int acc[4][4][4] = {};
    #pragma unroll
    for (int u = 0; u < 2; u++) {
        int c = tid + u * 256; int r = c >> 2, q = (c & 3) * 16;
        cp16(&As[0][r][q], &A [(size_t)(n0 + r) * NC + q]);
        cp16(&Bs[0][r][q], &Bm[(size_t)(m0 + r) * NC + q]);
    }
    CP_COMMIT();
    const int T = NC / KT8;   // 4
    for (int t = 0; t < T; t++) {
        if (t + 1 < T) {
            int k0 = (t + 1) * KT8, bi = (t + 1) & 1;
            #pragma unroll
            for (int u = 0; u < 2; u++) {
                int c = tid + u * 256; int r = c >> 2, q = (c & 3) * 16;
                cp16(&As[bi][r][q], &A [(size_t)(n0 + r) * NC + k0 + q]);
                cp16(&Bs[bi][r][q], &Bm[(size_t)(m0 + r) * NC + k0 + q]);
            }
            CP_COMMIT(); CP_WAIT1();
        } else CP_WAIT0();
        __syncthreads();
        int bi = t & 1;
        #pragma unroll
        for (int kk = 0; kk < KT8; kk += 32) {
            uint32_t af[4][4], bf[4][2];
            #pragma unroll
            for (int mi = 0; mi < 4; mi++) {
                int r = wr * 64 + mi * 16;
                af[mi][0] = *(const uint32_t*)&As[bi][r + g    ][kk + 4 * ti];
                af[mi][1] = *(const uint32_t*)&As[bi][r + g + 8][kk + 4 * ti];
                af[mi][2] = *(const uint32_t*)&As[bi][r + g    ][kk + 4 * ti + 16];
                af[mi][3] = *(const uint32_t*)&As[bi][r + g + 8][kk + 4 * ti + 16];
            }
            #pragma unroll
            for (int ni = 0; ni < 4; ni++) {
                int c = wc * 32 + ni * 8;
                bf[ni][0] = *(const uint32_t*)&Bs[bi][c + g][kk + 4 * ti];
                bf[ni][1] = *(const uint32_t*)&Bs[bi][c + g][kk + 4 * ti + 16];
            }
            #pragma unroll
            for (int mi = 0; mi < 4; mi++)
                #pragma unroll
                for (int ni = 0; ni < 4; ni++)
                    mma16832u8(acc[mi][ni], af[mi], bf[ni]);
        }
        __syncthreads();
    }
    int izq = __float2int_rn(zqp[0]), izk = __float2int_rn(zkp[0]);
    int c0i = NC * izq * izk;
    float sc = dqp[0] * dkp[0] * 0.0625f;
    const int* qs = g_qs + b * NHW;
    const int* ks = g_ks + b * NHW;
    int qsv[8], ksv[8];
    #pragma unroll
    for (int mi = 0; mi < 4; mi++) {
        qsv[2*mi]   = izk * qs[n0 + wr * 64 + mi * 16 + g];
        qsv[2*mi+1] = izk * qs[n0 + wr * 64 + mi * 16 + g + 8];
    }
    #pragma unroll
    for (int ni = 0; ni < 4; ni++) {
        ksv[2*ni]   = izq * ks[m0 + wc * 32 + ni * 8 + 2 * ti];
        ksv[2*ni+1] = izq * ks[m0 + wc * 32 + ni * 8 + 2 * ti + 1];
    }
    float* Sp = g_S + (size_t)b * NHW * NHW;
    #pragma unroll
    for (int mi = 0; mi < 4; mi++) {
        int n = n0 + wr * 64 + mi * 16 + g;
        #pragma unroll
        for (int ni = 0; ni < 4; ni++) {
            int m = m0 + wc * 32 + ni * 8 + 2 * ti;
            float2 v0, v1;
            v0.x = sc * (float)(acc[mi][ni][0] - ksv[2*ni]   - qsv[2*mi]   + c0i);
            v0.y = sc * (float)(acc[mi][ni][1] - ksv[2*ni+1] - qsv[2*mi]   + c0i);
            v1.x = sc * (float)(acc[mi][ni][2] - ksv[2*ni]   - qsv[2*mi+1] + c0i);
            v1.y = sc * (float)(acc[mi][ni][3] - ksv[2*ni+1] - qsv[2*mi+1] + c0i);
            *(float2*)&Sp[(size_t)n * NHW + m]       = v0;
            *(float2*)&Sp[(size_t)(n + 8) * NHW + m] = v1;
        }
    }
}

// ---------------- 7) softmax -> u8 codes + row code sums ----------------
__global__ void __launch_bounds__(256) softmax_kernel(const float* __restrict__ dwp,
                                                      const float* __restrict__ zwp) {
    size_t row = blockIdx.x;
    const float* s = g_S + row * NHW;
    uint8_t* a = g_a + row * NHW;
    int tid = threadIdx.x;
    float v[16];
    #pragma unroll
    for (int j = 0; j < 4; j++) {
        float4 t = *(const float4*)&s[(j * 256 + tid) * 4];
        v[4 * j + 0] = t.x; v[4 * j + 1] = t.y; v[4 * j + 2] = t.z; v[4 * j + 3] = t.w;
    }
    float mx = -3.4e38f;
    #pragma unroll
    for (int i = 0; i < 16; i++) mx = fmaxf(mx, v[i]);
    __shared__ float red[8];
    __shared__ int ired[8];
    #pragma unroll
    for (int o = 16; o; o >>= 1) mx = fmaxf(mx, __shfl_xor_sync(0xffffffffu, mx, o));
    if ((tid & 31) == 0) red[tid >> 5] = mx;
    __syncthreads();
    mx = red[0];
    #pragma unroll
    for (int k = 1; k < 8; k++) mx = fmaxf(mx, red[k]);
    __syncthreads();
    float sum = 0.f;
    #pragma unroll
    for (int i = 0; i < 16; i++) { v[i] = __expf(v[i] - mx); sum += v[i]; }
    #pragma unroll
    for (int o = 16; o; o >>= 1) sum += __shfl_xor_sync(0xffffffffu, sum, o);
    if ((tid & 31) == 0) red[tid >> 5] = sum;
    __syncthreads();
    sum = 0.f;
    #pragma unroll
    for (int k = 0; k < 8; k++) sum += red[k];
    float rinv = 1.0f / sum;
    float dinv = 1.0f / dwp[0], zw = zwp[0];
    int isum = 0;
    #pragma unroll
    for (int j = 0; j < 4; j++) {
        union { uint8_t c[4]; uint32_t u; } pk;
        #pragma unroll
        for (int l = 0; l < 4; l++) {
            float code = fq_raw(v[4 * j + l] * rinv, dinv, zw);
            pk.c[l] = (uint8_t)code;
            isum += (int)code;
        }
        *(uint32_t*)&a[(j * 256 + tid) * 4] = pk.u;
    }
    #pragma unroll
    for (int o = 16; o; o >>= 1) isum += __shfl_xor_sync(0xffffffffu, isum, o);
    if ((tid & 31) == 0) ired[tid >> 5] = isum;
    __syncthreads();
    if (tid == 0) {
        int t = 0;
        #pragma unroll
        for (int k = 0; k < 8; k++) t += ired[k];
        g_as[row] = t;
    }
}

// ---------------- 8) gemm2: int8 exact, hoT = scale*(V - zv*as - zw*vs + M*zv*zw) ----------------
__global__ void __launch_bounds__(256) gemm2_kernel(const float* __restrict__ dvp,
                                                    const float* __restrict__ zvp,
                                                    const float* __restrict__ dwp,
                                                    const float* __restrict__ zwp) {
    int b = blockIdx.z, n0 = blockIdx.x * 128, c0 = blockIdx.y * 128;
    const uint8_t* A  = g_a + (size_t)b * NHW * NHW;   // [n][m]
    const uint8_t* Bm = g_v + (size_t)b * NC * NHW;    // [c][m]
    __shared__ uint8_t As[2][128][SPB], Bs[2][128][SPB];
    int tid = threadIdx.x, warp = tid >> 5, lane = tid & 31;
    int g = lane >> 2, ti = lane & 3, wr = warp & 1, wc = warp >> 1;
    int acc[4][4][4] = {};
    #pragma unroll
    for (int u = 0; u < 2; u++) {
        int c = tid + u * 256; int r = c >> 2, q = (c & 3) * 16;
        cp16(&As[0][r][q], &A [(size_t)(n0 + r) * NHW + q]);
        cp16(&Bs[0][r][q], &Bm[(size_t)(c0 + r) * NHW + q]);
    }
    CP_COMMIT();
    const int T = NHW / KT8;  // 64
    for (int t = 0; t < T; t++) {
        if (t + 1 < T) {
            int k0 = (t + 1) * KT8, bi = (t + 1) & 1;
            #pragma unroll
            for (int u = 0; u < 2; u++) {
                int c = tid + u * 256; int r = c >> 2, q = (c & 3) * 16;
                cp16(&As[bi][r][q], &A [(size_t)(n0 + r) * NHW + k0 + q]);
                cp16(&Bs[bi][r][q], &Bm[(size_t)(c0 + r) * NHW + k0 + q]);
            }
            CP_COMMIT(); CP_WAIT1();
        } else CP_WAIT0();
        __syncthreads();
        int bi = t & 1;
        #pragma unroll
        for (int kk = 0; kk < KT8; kk += 32) {
            uint32_t af[4][4], bf[4][2];
            #pragma unroll
            for (int mi = 0; mi < 4; mi++) {
                int r = wr * 64 + mi * 16;
                af[mi][0] = *(const uint32_t*)&As[bi][r + g    ][kk + 4 * ti];
                af[mi][1] = *(const uint32_t*)&As[bi][r + g + 8][kk + 4 * ti];
                af[mi][2] = *(const uint32_t*)&As[bi][r + g    ][kk + 4 * ti + 16];
                af[mi][3] = *(const uint32_t*)&As[bi][r + g + 8][kk + 4 * ti + 16];
            }
            #pragma unroll
            for (int ni = 0; ni < 4; ni++) {
                int c = wc * 32 + ni * 8;
                bf[ni][0] = *(const uint32_t*)&Bs[bi][c + g][kk + 4 * ti];
                bf[ni][1] = *(const uint32_t*)&Bs[bi][c + g][kk + 4 * ti + 16];
            }
            #pragma unroll
            for (int mi = 0; mi < 4; mi++)
                #pragma unroll
                for (int ni = 0; ni < 4; ni++)
                    mma16832u8(acc[mi][ni], af[mi], bf[ni]);
        }
        __syncthreads();
    }
    int izv = __float2int_rn(zvp[0]), izw = __float2int_rn(zwp[0]);
    int c0i = NHW * izv * izw;
    float sc = dvp[0] * dwp[0];
    const int* as_ = g_as + b * NHW;
    const int* vs_ = g_vs + b * NC;
    int asv[8], vsv[8];
    #pragma unroll
    for (int mi = 0; mi < 4; mi++) {
        asv[2*mi]   = izv * as_[n0 + wr * 64 + mi * 16 + g];
        asv[2*mi+1] = izv * as_[n0 + wr * 64 + mi * 16 + g + 8];
    }
    #pragma unroll
    for (int ni = 0; ni < 4; ni++) {
        vsv[2*ni]   = izw * vs_[c0 + wc * 32 + ni * 8 + 2 * ti];
        vsv[2*ni+1] = izw * vs_[c0 + wc * 32 + ni * 8 + 2 * ti + 1];
    }
    __nv_bfloat16* Oh = g_hoT_hi + (size_t)b * NHW * NC;
    __nv_bfloat16* Ol = g_hoT_lo + (size_t)b * NHW * NC;
    #pragma unroll
    for (int mi = 0; mi < 4; mi++) {
        int n = n0 + wr * 64 + mi * 16 + g;
        #pragma unroll
        for (int ni = 0; ni < 4; ni++) {
            int c = c0 + wc * 32 + ni * 8 + 2 * ti;
            #pragma unroll
            for (int half = 0; half < 2; half++) {
                float v0 = sc * (float)(acc[mi][ni][2*half]   - vsv[2*ni]   - asv[2*mi+half] + c0i);
                float v1 = sc * (float)(acc[mi][ni][2*half+1] - vsv[2*ni+1] - asv[2*mi+half] + c0i);
                __nv_bfloat16 h0 = __float2bfloat16(v0);
                __nv_bfloat16 h1 = __float2bfloat16(v1);
                union { __nv_bfloat16 h[2]; uint32_t u; } ph, pl;
                ph.h[0] = h0; ph.h[1] = h1;
                pl.h[0] = __float2bfloat16(v0 - __bfloat162float(h0));
                pl.h[1] = __float2bfloat16(v1 - __bfloat162float(h1));
                size_t off = (size_t)(n + 8 * half) * NC + c;
                *(uint32_t*)&Oh[off] = ph.u;
                *(uint32_t*)&Ol[off] = pl.u;
            }
        }
    }
}

// ---------------- 9) proj: split-bf16 mma + bias + residual ----------------
__global__ void __launch_bounds__(256) proj_kernel(const float* __restrict__ x,
                                                   const float* __restrict__ bias,
                                                   float* __restrict__ out) {
    int b = blockIdx.z;
    int n0 = blockIdx.x * 128, o0 = blockIdx.y * 128;
    const __nv_bfloat16* Wh = g_w_hi + 3 * NC * NC;
    const __nv_bfloat16* Wl = g_w_lo + 3 * NC * NC;
    const __nv_bfloat16* Ahg = g_hoT_hi + (size_t)b * NHW * NC;
    const __nv_bfloat16* Alg = g_hoT_lo + (size_t)b * NHW * NC;

    __shared__ union SmU {
        struct { __nv_bfloat16 Ah[128][SP], Al[128][SP], Bh[128][SP], Bl[128][SP]; } m;
        float tf[64][132];
    } sm;

    int tid = threadIdx.x, warp = tid >> 5, lane = tid & 31;
    int g = lane >> 2, ti = lane & 3, wr = warp & 1, wc = warp >> 1;
    float acc[4][4][4] = {};

    for (int k0 = 0; k0 < NC; k0 += KT) {
        #pragma unroll
        for (int u = 0; u < 2; u++) {
            int c = tid + u * 256; int r = c >> 2, q = (c & 3) * 8;
            cp16(&sm.m.Ah[r][q], &Ahg[(size_t)(n0 + r) * NC + k0 + q]);
            cp16(&sm.m.Al[r][q], &Alg[(size_t)(n0 + r) * NC + k0 + q]);
            cp16(&sm.m.Bh[r][q], &Wh[(o0 + r) * NC + k0 + q]);
            cp16(&sm.m.Bl[r][q], &Wl[(o0 + r) * NC + k0 + q]);
        }
        CP_COMMIT(); CP_WAIT0();
        __syncthreads();
        #pragma unroll
        for (int kk = 0; kk < KT; kk += 16) {
            uint32_t ah[4][4], al[4][4], bh[4][2], bl[4][2];
            #pragma unroll
            for (int mi = 0; mi < 4; mi++) {
                int r = wr * 64 + mi * 16;
                ah[mi][0] = *(const uint32_t*)&sm.m.Ah[r + g    ][kk + 2 * ti];
                ah[mi][1] = *(const uint32_t*)&sm.m.Ah[r + g + 8][kk + 2 * ti];
                ah[mi][2] = *(const uint32_t*)&sm.m.Ah[r + g    ][kk + 2 * ti + 8];
                ah[mi][3] = *(const uint32_t*)&sm.m.Ah[r + g + 8][kk + 2 * ti + 8];
                al[mi][0] = *(const uint32_t*)&sm.m.Al[r + g    ][kk + 2 * ti];
                al[mi][1] = *(const uint32_t*)&sm.m.Al[r + g + 8][kk + 2 * ti];
                al[mi][2] = *(const uint32_t*)&sm.m.Al[r + g    ][kk + 2 * ti + 8];
                al[mi][3] = *(const uint32_t*)&sm.m.Al[r + g + 8][kk + 2 * ti + 8];
            }
            #pragma unroll
            for (int ni = 0; ni < 4; ni++) {
                int c = wc * 32 + ni * 8;
                bh[ni][0] = *(const uint32_t*)&sm.m.Bh[c + g][kk + 2 * ti];
                bh[ni][1] = *(const uint32_t*)&sm.m.Bh[c + g][kk + 2 * ti + 8];
                bl[ni][0] = *(const uint32_t*)&sm.m.Bl[c + g][kk + 2 * ti];
                bl[ni][1] = *(const uint32_t*)&sm.m.Bl[c + g][kk + 2 * ti + 8];
            }
            #pragma unroll
            for (int mi = 0; mi < 4; mi++)
                #pragma unroll
                for (int ni = 0; ni < 4; ni++) {
                    mma16816(acc[mi][ni], ah[mi], bh[ni]);
                    mma16816(acc[mi][ni], ah[mi], bl[ni]);
                    mma16816(acc[mi][ni], al[mi], bh[ni]);
                }
        }
        __syncthreads();
    }

    #pragma unroll
    for (int hp = 0; hp < 2; hp++) {
        if ((wc >> 1) == hp) {
            #pragma unroll
            for (int mi = 0; mi < 4; mi++) {
                int nl = wr * 64 + mi * 16 + g;
                #pragma unroll
                for (int ni = 0; ni < 4; ni++) {
                    int ol = (wc & 1) * 32 + ni * 8 + 2 * ti;
                    sm.tf[ol    ][nl    ] = acc[mi][ni][0];
                    sm.tf[ol + 1][nl    ] = acc[mi][ni][1];
                    sm.tf[ol    ][nl + 8] = acc[mi][ni][2];
                    sm.tf[ol + 1][nl + 8] = acc[mi][ni][3];
                }
            }
        }
        __syncthreads();
        int r = tid >> 2, qn = (tid & 3) * 32;
        int o = o0 + hp * 64 + r;
        float bo = bias[o];
        size_t base = ((size_t)b * NC + o) * NHW + n0 + qn;
        #pragma unroll
        for (int j = 0; j < 32; j += 4) {
            float4 xv = *(const float4*)&x[base + j];
            float4 tv = *(const float4*)&sm.tf[r][qn + j];
            float4 rv;
            rv.x = xv.x + tv.x + bo; rv.y = xv.y + tv.y + bo;
            rv.z = xv.z + tv.z + bo; rv.w = xv.w + tv.w + bo;
            *(float4*)&out[base + j] = rv;
        }
        __syncthreads();
    }
}

// ---------------- launch ----------------
extern "C" void kernel_launch(void* const* d_in, const int* in_sizes, int n_in,
                              void* d_out, int out_size) {
    const float* x      = (const float*)d_in[0];
    const float* gns    = (const float*)d_in[1];
    const float* gnb    = (const float*)d_in[2];
    const float* wq     = (const float*)d_in[3];
    const float* bq     = (const float*)d_in[4];
    const float* wk     = (const float*)d_in[5];
    const float* bk     = (const float*)d_in[6];
    const float* wv     = (const float*)d_in[7];
    const float* bv     = (const float*)d_in[8];
    const float* wproj  = (const float*)d_in[9];
    const float* bproj  = (const float*)d_in[10];
    const float* dq     = (const float*)d_in[11];
    const float* zq     = (const float*)d_in[12];
    const float* dk     = (const float*)d_in[13];
    const float* zk     = (const float*)d_in[14];
    const float* dv     = (const float*)d_in[15];
    const float* zv     = (const float*)d_in[16];
    const float* dw     = (const float*)d_in[17];
    const float* zw     = (const float*)d_in[18];
    float* out = (float*)d_out;

    gn_kernel<<<NB * 32, 256>>>(x, gns, gnb);
    wsplit_kernel<<<256, 256>>>(wq, wk, wv, wproj);
    qkv_kernel<<<dim3(NHW / 128, NC / 128, NB * 3), 256>>>(
        bq, bk, bv, dq, zq, dk, zk, dv, zv);
    sums_qk_kernel<<<2 * NB * NHW / 8, 256>>>();
    vsum_kernel<<<NB * NC / 8, 256>>>();
    gemm1_kernel<<<dim3(NHW / 128, NHW / 128, NB), 256>>>(dq, zq, dk, zk);
    softmax_kernel<<<NB * NHW, 256>>>(dw, zw);
    gemm2_kernel<<<dim3(NHW / 128, NC / 128, NB), 256>>>(dv, zv, dw, zw);
    proj_kernel<<<dim3(NHW / 128, NC / 128, NB), 256>>>(x, bproj, out);
}

// round 6
// speedup vs baseline: 2.5764x; 2.5764x over previous
#include <cuda_runtime.h>
#include <cuda_bf16.h>
#include <cstdint>

#define NB 4
#define NC 256
#define NHW 4096
#define KT 32
#define SP 40   // padded smem row stride (bf16 elems): 80B, conflict-free for ldmatrix

// ---------------- scratch ----------------
__device__ __nv_bfloat16 g_hT_hi[NB*NHW*NC];
__device__ __nv_bfloat16 g_hT_lo[NB*NHW*NC];
__device__ __nv_bfloat16 g_w_hi[4*NC*NC];   // q,k,v,proj
__device__ __nv_bfloat16 g_w_lo[4*NC*NC];
__device__ __nv_bfloat16 g_q[NB*NHW*NC];    // quantized q codes [b][n][c]
__device__ __nv_bfloat16 g_k[NB*NHW*NC];    // quantized k codes [b][m][c]
__device__ __nv_bfloat16 g_v[NB*NC*NHW];    // quantized v codes [b][c][m]
__device__ float         g_S[(size_t)NB*NHW*NHW];
__device__ __nv_bfloat16 g_a[(size_t)NB*NHW*NHW];  // quantized attn codes [b][n][m]
__device__ __nv_bfloat16 g_hoT_hi[NB*NHW*NC];
__device__ __nv_bfloat16 g_hoT_lo[NB*NHW*NC];

// ---------------- helpers ----------------
__device__ __forceinline__ void mma16816(float d[4], const uint32_t a[4], const uint32_t b[2]) {
    asm volatile(
        "mma.sync.aligned.m16n8k16.row.col.f32.bf16.bf16.f32 "
        "{%0,%1,%2,%3},{%4,%5,%6,%7},{%8,%9},{%0,%1,%2,%3};\n"
        : "+f"(d[0]), "+f"(d[1]), "+f"(d[2]), "+f"(d[3])
        : "r"(a[0]), "r"(a[1]), "r"(a[2]), "r"(a[3]), "r"(b[0]), "r"(b[1]));
}
__device__ __forceinline__ void ldsm4(uint32_t r[4], const void* p) {
    uint32_t a = (uint32_t)__cvta_generic_to_shared(p);
    asm volatile("ldmatrix.sync.aligned.m8n8.x4.shared.b16 {%0,%1,%2,%3},[%4];\n"
        : "=r"(r[0]), "=r"(r[1]), "=r"(r[2]), "=r"(r[3]) : "r"(a));
}
__device__ __forceinline__ void cp16(void* s, const void* g) {
    uint32_t sa = (uint32_t)__cvta_generic_to_shared(s);
    asm volatile("cp.async.cg.shared.global [%0],[%1],16;\n" :: "r"(sa), "l"(g));
}
#define CP_COMMIT() asm volatile("cp.async.commit_group;\n")
#define CP_WAIT0()  asm volatile("cp.async.wait_group 0;\n")
#define CP_WAIT1()  asm volatile("cp.async.wait_group 1;\n")

__device__ __forceinline__ float fq_code(float v, float dinv, float zp) {
    float q = rintf(v * dinv) + zp;
    q = fminf(fmaxf(q, 0.0f), 255.0f);
    return q - zp;
}

// ---------------- 1) GroupNorm -> hT hi/lo [b][n][c] ----------------
__global__ void __launch_bounds__(256) gn_kernel(const float* __restrict__ x,
                                                 const float* __restrict__ gam,
                                                 const float* __restrict__ bet) {
    int b = blockIdx.x >> 5, gr = blockIdx.x & 31;
    const float* xp = x + ((size_t)(b * NC) + gr * 8) * NHW;
    int tid = threadIdx.x;
    const int Nf4 = 8 * NHW / 4;
    const float4* x4 = (const float4*)xp;
    float s = 0.f, ss = 0.f;
    for (int i = tid; i < Nf4; i += 256) {
        float4 v = x4[i];
        s  += v.x + v.y + v.z + v.w;
        ss += v.x * v.x + v.y * v.y + v.z * v.z + v.w * v.w;
    }
    __shared__ float rs[8], rss[8], s_sc[8], s_sh[8];
    #pragma unroll
    for (int o = 16; o; o >>= 1) {
        s  += __shfl_down_sync(0xffffffffu, s, o);
        ss += __shfl_down_sync(0xffffffffu, ss, o);
    }
    if ((tid & 31) == 0) { rs[tid >> 5] = s; rss[tid >> 5] = ss; }
    __syncthreads();
    float ts = 0.f, tss = 0.f;
    #pragma unroll
    for (int k = 0; k < 8; k++) { ts += rs[k]; tss += rss[k]; }
    const float inv = 1.0f / (float)(8 * NHW);
    float mu = ts * inv;
    float var = tss * inv - mu * mu;
    float rstd = 1.0f / sqrtf(var + 1e-6f);
    if (tid < 8) {
        float gm = gam[gr * 8 + tid];
        s_sc[tid] = gm * rstd;
        s_sh[tid] = bet[gr * 8 + tid] - mu * gm * rstd;
    }
    __syncthreads();
    __nv_bfloat16* Hh = g_hT_hi + (size_t)b * NHW * NC + gr * 8;
    __nv_bfloat16* Hl = g_hT_lo + (size_t)b * NHW * NC + gr * 8;
    for (int n = tid; n < NHW; n += 256) {
        union { __nv_bfloat16 h[8]; uint4 u; } ph, pl;
        #pragma unroll
        for (int c = 0; c < 8; c++) {
            float v = xp[(size_t)c * NHW + n] * s_sc[c] + s_sh[c];
            __nv_bfloat16 hi = __float2bfloat16(v);
            ph.h[c] = hi;
            pl.h[c] = __float2bfloat16(v - __bfloat162float(hi));
        }
        *(uint4*)&Hh[(size_t)n * NC] = ph.u;
        *(uint4*)&Hl[(size_t)n * NC] = pl.u;
    }
}

// ---------------- 2) weight split ----------------
__global__ void __launch_bounds__(256) wsplit_kernel(const float* __restrict__ wq,
                                                     const float* __restrict__ wk,
                                                     const float* __restrict__ wv,
                                                     const float* __restrict__ wp) {
    int idx = blockIdx.x * 256 + threadIdx.x;
    const float* ws[4] = {wq, wk, wv, wp};
    #pragma unroll
    for (int m = 0; m < 4; m++) {
        float v = ws[m][idx];
        __nv_bfloat16 hi = __float2bfloat16(v);
        g_w_hi[m * NC * NC + idx] = hi;
        g_w_lo[m * NC * NC + idx] = __float2bfloat16(v - __bfloat162float(hi));
    }
}

// ---------------- 3) QKV: split-bf16 mma conv + quantize (ldmatrix) ----------------
__global__ void __launch_bounds__(256) qkv_kernel(
    const float* __restrict__ bq, const float* __restrict__ bk, const float* __restrict__ bv,
    const float* __restrict__ dqp, const float* __restrict__ zqp,
    const float* __restrict__ dkp, const float* __restrict__ zkp,
    const float* __restrict__ dvp, const float* __restrict__ zvp) {
    int z = blockIdx.z;
    int b = z / 3, which = z - b * 3;
    const __nv_bfloat16* Wh = g_w_hi + which * NC * NC;
    const __nv_bfloat16* Wl = g_w_lo + which * NC * NC;
    const float* bias;
    float d, zp;
    if (which == 0)      { bias = bq; d = dqp[0]; zp = zqp[0]; }
    else if (which == 1) { bias = bk; d = dkp[0]; zp = zkp[0]; }
    else                 { bias = bv; d = dvp[0]; zp = zvp[0]; }
    int n0 = blockIdx.x * 128, o0 = blockIdx.y * 128;
    const __nv_bfloat16* Ahg = g_hT_hi + (size_t)b * NHW * NC;
    const __nv_bfloat16* Alg = g_hT_lo + (size_t)b * NHW * NC;

    __shared__ union SmU {
        struct { __nv_bfloat16 Ah[128][SP], Al[128][SP], Bh[128][SP], Bl[128][SP]; } m;
        __nv_bfloat16 tb[128][136];
    } sm;

    int tid = threadIdx.x, warp = tid >> 5, lane = tid & 31;
    int g = lane >> 2, ti = lane & 3, wr = warp & 1, wc = warp >> 1;
    // ldmatrix lane addressing
    int la  = lane & 15;                 // A row within 16
    int kA  = ((lane >> 4) & 1) * 8;     // A k-offset
    int lb  = (lane & 7) + ((lane >> 4) & 1) * 8;   // B row within 16
    int kB  = ((lane >> 3) & 1) * 8;     // B k-offset
    float acc[4][4][4] = {};

    for (int k0 = 0; k0 < NC; k0 += KT) {
        #pragma unroll
        for (int u = 0; u < 2; u++) {
            int c = tid + u * 256; int r = c >> 2, q = (c & 3) * 8;
            cp16(&sm.m.Ah[r][q], &Ahg[(size_t)(n0 + r) * NC + k0 + q]);
            cp16(&sm.m.Al[r][q], &Alg[(size_t)(n0 + r) * NC + k0 + q]);
            cp16(&sm.m.Bh[r][q], &Wh[(o0 + r) * NC + k0 + q]);
            cp16(&sm.m.Bl[r][q], &Wl[(o0 + r) * NC + k0 + q]);
        }
        CP_COMMIT(); CP_WAIT0();
        __syncthreads();
        #pragma unroll
        for (int kk = 0; kk < KT; kk += 16) {
            uint32_t ah[4][4], al[4][4], bh[2][4], bl[2][4];
            #pragma unroll
            for (int mi = 0; mi < 4; mi++) {
                int r = wr * 64 + mi * 16 + la;
                ldsm4(ah[mi], &sm.m.Ah[r][kk + kA]);
                ldsm4(al[mi], &sm.m.Al[r][kk + kA]);
            }
            #pragma unroll
            for (int nj = 0; nj < 2; nj++) {
                int c = wc * 32 + nj * 16 + lb;
                ldsm4(bh[nj], &sm.m.Bh[c][kk + kB]);
                ldsm4(bl[nj], &sm.m.Bl[c][kk + kB]);
            }
            #pragma unroll
            for (int mi = 0; mi < 4; mi++)
                #pragma unroll
                for (int ni = 0; ni < 4; ni++) {
                    mma16816(acc[mi][ni], ah[mi], &bh[ni >> 1][(ni & 1) * 2]);
                    mma16816(acc[mi][ni], ah[mi], &bl[ni >> 1][(ni & 1) * 2]);
                    mma16816(acc[mi][ni], al[mi], &bh[ni >> 1][(ni & 1) * 2]);
                }
        }
        __syncthreads();
    }

    float dinv = 1.0f / d;
    if (which < 2) {
        __nv_bfloat16* Out = (which == 0 ? g_q : g_k) + (size_t)b * NHW * NC;
        #pragma unroll
        for (int mi = 0; mi < 4; mi++) {
            int n = n0 + wr * 64 + mi * 16 + g;
            #pragma unroll
            for (int ni = 0; ni < 4; ni++) {
                int o = o0 + wc * 32 + ni * 8 + 2 * ti;
                float b0 = bias[o], b1 = bias[o + 1];
                union { __nv_bfloat16 h[2]; uint32_t u; } p0, p1;
                p0.h[0] = __float2bfloat16(fq_code(acc[mi][ni][0] + b0, dinv, zp));
                p0.h[1] = __float2bfloat16(fq_code(acc[mi][ni][1] + b1, dinv, zp));
                p1.h[0] = __float2bfloat16(fq_code(acc[mi][ni][2] + b0, dinv, zp));
                p1.h[1] = __float2bfloat16(fq_code(acc[mi][ni][3] + b1, dinv, zp));
                *(uint32_t*)&Out[(size_t)n * NC + o]       = p0.u;
                *(uint32_t*)&Out[(size_t)(n + 8) * NC + o] = p1.u;
            }
        }
    } else {
        #pragma unroll
        for (int mi = 0; mi < 4; mi++) {
            int nl = wr * 64 + mi * 16 + g;
            #pragma unroll
            for (int ni = 0; ni < 4; ni++) {
                int ol = wc * 32 + ni * 8 + 2 * ti;
                float b0 = bias[o0 + ol], b1 = bias[o0 + ol + 1];
                sm.tb[ol    ][nl    ] = __float2bfloat16(fq_code(acc[mi][ni][0] + b0, dinv, zp));
                sm.tb[ol + 1][nl    ] = __float2bfloat16(fq_code(acc[mi][ni][1] + b1, dinv, zp));
                sm.tb[ol    ][nl + 8] = __float2bfloat16(fq_code(acc[mi][ni][2] + b0, dinv, zp));
                sm.tb[ol + 1][nl + 8] = __float2bfloat16(fq_code(acc[mi][ni][3] + b1, dinv, zp));
            }
        }
        __syncthreads();
        int r = tid >> 1, half = (tid & 1) * 64;
        #pragma unroll
        for (int j = 0; j < 64; j += 8)
            *(uint4*)&g_v[((size_t)b * NC + o0 + r) * NHW + n0 + half + j] =
                *(uint4*)&sm.tb[r][half + j];
    }
}

// ---------------- 4) gemm1: S = q . k^T (exact via bf16 mma, ldmatrix) ----------------
__global__ void __launch_bounds__(256) gemm1_kernel(const float* __restrict__ dqp,
                                                    const float* __restrict__ dkp) {
    int b = blockIdx.z, m0 = blockIdx.x * 128, n0 = blockIdx.y * 128;
    const __nv_bfloat16* A  = g_q + (size_t)b * NHW * NC;
    const __nv_bfloat16* Bm = g_k + (size_t)b * NHW * NC;
    __shared__ __nv_bfloat16 As[2][128][SP], Bs[2][128][SP];
    int tid = threadIdx.x, warp = tid >> 5, lane = tid & 31;
    int g = lane >> 2, ti = lane & 3, wr = warp & 1, wc = warp >> 1;
    int la  = lane & 15;
    int kA  = ((lane >> 4) & 1) * 8;
    int lb  = (lane & 7) + ((lane >> 4) & 1) * 8;
    int kB  = ((lane >> 3) & 1) * 8;
    float acc[4][4][4] = {};
    #pragma unroll
    for (int u = 0; u < 2; u++) {
        int c = tid + u * 256; int r = c >> 2, q = (c & 3) * 8;
        cp16(&As[0][r][q], &A [(size_t)(n0 + r) * NC + q]);
        cp16(&Bs[0][r][q], &Bm[(size_t)(m0 + r) * NC + q]);
    }
    CP_COMMIT();
    const int T = NC / KT;
    for (int t = 0; t < T; t++) {
        if (t + 1 < T) {
            int k0 = (t + 1) * KT, bi = (t + 1) & 1;
            #pragma unroll
            for (int u = 0; u < 2; u++) {
                int c = tid + u * 256; int r = c >> 2, q = (c & 3) * 8;
                cp16(&As[bi][r][q], &A [(size_t)(n0 + r) * NC + k0 + q]);
                cp16(&Bs[bi][r][q], &Bm[(size_t)(m0 + r) * NC + k0 + q]);
            }
            CP_COMMIT(); CP_WAIT1();
        } else CP_WAIT0();
        __syncthreads();
        int bi = t & 1;
        #pragma unroll
        for (int kk = 0; kk < KT; kk += 16) {
            uint32_t af[4][4], bf[2][4];
            #pragma unroll
            for (int mi = 0; mi < 4; mi++)
                ldsm4(af[mi], &As[bi][wr * 64 + mi * 16 + la][kk + kA]);
            #pragma unroll
            for (int nj = 0; nj < 2; nj++)
                ldsm4(bf[nj], &Bs[bi][wc * 32 + nj * 16 + lb][kk + kB]);
            #pragma unroll
            for (int mi = 0; mi < 4; mi++)
                #pragma unroll
                for (int ni = 0; ni < 4; ni++)
                    mma16816(acc[mi][ni], af[mi], &bf[ni >> 1][(ni & 1) * 2]);
        }
        __syncthreads();
    }
    float sc = dqp[0] * dkp[0] * 0.0625f;
    float* Sp = g_S + (size_t)b * NHW * NHW;
    #pragma unroll
    for (int mi = 0; mi < 4; mi++) {
        int n = n0 + wr * 64 + mi * 16 + g;
        #pragma unroll
        for (int ni = 0; ni < 4; ni++) {
            int m = m0 + wc * 32 + ni * 8 + 2 * ti;
            *(float2*)&Sp[(size_t)n * NHW + m]       = make_float2(acc[mi][ni][0] * sc, acc[mi][ni][1] * sc);
            *(float2*)&Sp[(size_t)(n + 8) * NHW + m] = make_float2(acc[mi][ni][2] * sc, acc[mi][ni][3] * sc);
        }
    }
}

// ---------------- 5) softmax + 8-bit quantize ----------------
__global__ void __launch_bounds__(256) softmax_kernel(const float* __restrict__ dwp,
                                                      const float* __restrict__ zwp) {
    size_t row = blockIdx.x;
    const float* s = g_S + row * NHW;
    __nv_bfloat16* a = g_a + row * NHW;
    int tid = threadIdx.x;
    float v[16];
    #pragma unroll
    for (int j = 0; j < 4; j++) {
        float4 t = *(const float4*)&s[(j * 256 + tid) * 4];
        v[4 * j + 0] = t.x; v[4 * j + 1] = t.y; v[4 * j + 2] = t.z; v[4 * j + 3] = t.w;
    }
    float mx = -3.4e38f;
    #pragma unroll
    for (int i = 0; i < 16; i++) mx = fmaxf(mx, v[i]);
    __shared__ float red[8];
    #pragma unroll
    for (int o = 16; o; o >>= 1) mx = fmaxf(mx, __shfl_xor_sync(0xffffffffu, mx, o));
    if ((tid & 31) == 0) red[tid >> 5] = mx;
    __syncthreads();
    mx = red[0];
    #pragma unroll
    for (int k = 1; k < 8; k++) mx = fmaxf(mx, red[k]);
    __syncthreads();
    float sum = 0.f;
    #pragma unroll
    for (int i = 0; i < 16; i++) { v[i] = __expf(v[i] - mx); sum += v[i]; }
    #pragma unroll
    for (int o = 16; o; o >>= 1) sum += __shfl_xor_sync(0xffffffffu, sum, o);
    if ((tid & 31) == 0) red[tid >> 5] = sum;
    __syncthreads();
    sum = 0.f;
    #pragma unroll
    for (int k = 0; k < 8; k++) sum += red[k];
    float rinv = 1.0f / sum;
    float dinv = 1.0f / dwp[0], zw = zwp[0];
    #pragma unroll
    for (int j = 0; j < 4; j++) {
        union { __nv_bfloat16 h[4]; uint2 u; } pk;
        #pragma unroll
        for (int l = 0; l < 4; l++)
            pk.h[l] = __float2bfloat16(fq_code(v[4 * j + l] * rinv, dinv, zw));
        *(uint2*)&a[(j * 256 + tid) * 4] = pk.u;
    }
}

// ---------------- 6) gemm2: hoT = a . v^T, emit split hi/lo (ldmatrix) ----------------
__global__ void __launch_bounds__(256) gemm2_kernel(const float* __restrict__ dvp,
                                                    const float* __restrict__ dwp) {
    int b = blockIdx.z, n0 = blockIdx.x * 128, c0 = blockIdx.y * 128;
    const __nv_bfloat16* A  = g_a + (size_t)b * NHW * NHW;   // [n][m]
    const __nv_bfloat16* Bm = g_v + (size_t)b * NC * NHW;    // [c][m]
    __shared__ __nv_bfloat16 As[2][128][SP], Bs[2][128][SP];
    int tid = threadIdx.x, warp = tid >> 5, lane = tid & 31;
    int g = lane >> 2, ti = lane & 3, wr = warp & 1, wc = warp >> 1;
    int la  = lane & 15;
    int kA  = ((lane >> 4) & 1) * 8;
    int lb  = (lane & 7) + ((lane >> 4) & 1) * 8;
    int kB  = ((lane >> 3) & 1) * 8;
    float acc[4][4][4] = {};
    #pragma unroll
    for (int u = 0; u < 2; u++) {
        int c = tid + u * 256; int r = c >> 2, q = (c & 3) * 8;
        cp16(&As[0][r][q], &A [(size_t)(n0 + r) * NHW + q]);
        cp16(&Bs[0][r][q], &Bm[(size_t)(c0 + r) * NHW + q]);
    }
    CP_COMMIT();
    const int T = NHW / KT;
    for (int t = 0; t < T; t++) {
        if (t + 1 < T) {
            int k0 = (t + 1) * KT, bi = (t + 1) & 1;
            #pragma unroll
            for (int u = 0; u < 2; u++) {
                int c = tid + u * 256; int r = c >> 2, q = (c & 3) * 8;
                cp16(&As[bi][r][q], &A [(size_t)(n0 + r) * NHW + k0 + q]);
                cp16(&Bs[bi][r][q], &Bm[(size_t)(c0 + r) * NHW + k0 + q]);
            }
            CP_COMMIT(); CP_WAIT1();
        } else CP_WAIT0();
        __syncthreads();
        int bi = t & 1;
        #pragma unroll
        for (int kk = 0; kk < KT; kk += 16) {
            uint32_t af[4][4], bf[2][4];
            #pragma unroll
            for (int mi = 0; mi < 4; mi++)
                ldsm4(af[mi], &As[bi][wr * 64 + mi * 16 + la][kk + kA]);
            #pragma unroll
            for (int nj = 0; nj < 2; nj++)
                ldsm4(bf[nj], &Bs[bi][wc * 32 + nj * 16 + lb][kk + kB]);
            #pragma unroll
            for (int mi = 0; mi < 4; mi++)
                #pragma unroll
                for (int ni = 0; ni < 4; ni++)
                    mma16816(acc[mi][ni], af[mi], &bf[ni >> 1][(ni & 1) * 2]);
        }
        __syncthreads();
    }
    float sc = dvp[0] * dwp[0];
    __nv_bfloat16* Oh = g_hoT_hi + (size_t)b * NHW * NC;
    __nv_bfloat16* Ol = g_hoT_lo + (size_t)b * NHW * NC;
    #pragma unroll
    for (int mi = 0; mi < 4; mi++) {
        int n = n0 + wr * 64 + mi * 16 + g;
        #pragma unroll
        for (int ni = 0; ni < 4; ni++) {
            int c = c0 + wc * 32 + ni * 8 + 2 * ti;
            #pragma unroll
            for (int half = 0; half < 2; half++) {
                float v0 = acc[mi][ni][2 * half] * sc;
                float v1 = acc[mi][ni][2 * half + 1] * sc;
                __nv_bfloat16 h0 = __float2bfloat16(v0);
                __nv_bfloat16 h1 = __float2bfloat16(v1);
                union { __nv_bfloat16 h[2]; uint32_t u; } ph, pl;
                ph.h[0] = h0; ph.h[1] = h1;
                pl.h[0] = __float2bfloat16(v0 - __bfloat162float(h0));
                pl.h[1] = __float2bfloat16(v1 - __bfloat162float(h1));
                size_t off = (size_t)(n + 8 * half) * NC + c;
                *(uint32_t*)&Oh[off] = ph.u;
                *(uint32_t*)&Ol[off] = pl.u;
            }
        }
    }
}

// ---------------- 7) proj: split-bf16 mma + bias + residual (ldmatrix) ----------------
__global__ void __launch_bounds__(256) proj_kernel(const float* __restrict__ x,
                                                   const float* __restrict__ bias,
                                                   float* __restrict__ out) {
    int b = blockIdx.z;
    int n0 = blockIdx.x * 128, o0 = blockIdx.y * 128;
    const __nv_bfloat16* Wh = g_w_hi + 3 * NC * NC;
    const __nv_bfloat16* Wl = g_w_lo + 3 * NC * NC;
    const __nv_bfloat16* Ahg = g_hoT_hi + (size_t)b * NHW * NC;
    const __nv_bfloat16* Alg = g_hoT_lo + (size_t)b * NHW * NC;

    __shared__ union SmU {
        struct { __nv_bfloat16 Ah[128][SP], Al[128][SP], Bh[128][SP], Bl[128][SP]; } m;
        float tf[64][132];
    } sm;

    int tid = threadIdx.x, warp = tid >> 5, lane = tid & 31;
    int g = lane >> 2, ti = lane & 3, wr = warp & 1, wc = warp >> 1;
    int la  = lane & 15;
    int kA  = ((lane >> 4) & 1) * 8;
    int lb  = (lane & 7) + ((lane >> 4) & 1) * 8;
    int kB  = ((lane >> 3) & 1) * 8;
    float acc[4][4][4] = {};

    for (int k0 = 0; k0 < NC; k0 += KT) {
        #pragma unroll
        for (int u = 0; u < 2; u++) {
            int c = tid + u * 256; int r = c >> 2, q = (c & 3) * 8;
            cp16(&sm.m.Ah[r][q], &Ahg[(size_t)(n0 + r) * NC + k0 + q]);
            cp16(&sm.m.Al[r][q], &Alg[(size_t)(n0 + r) * NC + k0 + q]);
            cp16(&sm.m.Bh[r][q], &Wh[(o0 + r) * NC + k0 + q]);
            cp16(&sm.m.Bl[r][q], &Wl[(o0 + r) * NC + k0 + q]);
        }
        CP_COMMIT(); CP_WAIT0();
        __syncthreads();
        #pragma unroll
        for (int kk = 0; kk < KT; kk += 16) {
            uint32_t ah[4][4], al[4][4], bh[2][4], bl[2][4];
            #pragma unroll
            for (int mi = 0; mi < 4; mi++) {
                int r = wr * 64 + mi * 16 + la;
                ldsm4(ah[mi], &sm.m.Ah[r][kk + kA]);
                ldsm4(al[mi], &sm.m.Al[r][kk + kA]);
            }
            #pragma unroll
            for (int nj = 0; nj < 2; nj++) {
                int c = wc * 32 + nj * 16 + lb;
                ldsm4(bh[nj], &sm.m.Bh[c][kk + kB]);
                ldsm4(bl[nj], &sm.m.Bl[c][kk + kB]);
            }
            #pragma unroll
            for (int mi = 0; mi < 4; mi++)
                #pragma unroll
                for (int ni = 0; ni < 4; ni++) {
                    mma16816(acc[mi][ni], ah[mi], &bh[ni >> 1][(ni & 1) * 2]);
                    mma16816(acc[mi][ni], ah[mi], &bl[ni >> 1][(ni & 1) * 2]);
                    mma16816(acc[mi][ni], al[mi], &bh[ni >> 1][(ni & 1) * 2]);
                }
        }
        __syncthreads();
    }

    // two-pass fp32 transpose epilogue with residual + bias
    #pragma unroll
    for (int hp = 0; hp < 2; hp++) {
        if ((wc >> 1) == hp) {
            #pragma unroll
            for (int mi = 0; mi < 4; mi++) {
                int nl = wr * 64 + mi * 16 + g;
                #pragma unroll
                for (int ni = 0; ni < 4; ni++) {
                    int ol = (wc & 1) * 32 + ni * 8 + 2 * ti;
                    sm.tf[ol    ][nl    ] = acc[mi][ni][0];
                    sm.tf[ol + 1][nl    ] = acc[mi][ni][1];
                    sm.tf[ol    ][nl + 8] = acc[mi][ni][2];
                    sm.tf[ol + 1][nl + 8] = acc[mi][ni][3];
                }
            }
        }
        __syncthreads();
        int r = tid >> 2, qn = (tid & 3) * 32;
        int o = o0 + hp * 64 + r;
        float bo = bias[o];
        size_t base = ((size_t)b * NC + o) * NHW + n0 + qn;
        #pragma unroll
        for (int j = 0; j < 32; j += 4) {
            float4 xv = *(const float4*)&x[base + j];
            float4 tv = *(const float4*)&sm.tf[r][qn + j];
            float4 rv;
            rv.x = xv.x + tv.x + bo; rv.y = xv.y + tv.y + bo;
            rv.z = xv.z + tv.z + bo; rv.w = xv.w + tv.w + bo;
            *(float4*)&out[base + j] = rv;
        }
        __syncthreads();
    }
}

// ---------------- launch ----------------
extern "C" void kernel_launch(void* const* d_in, const int* in_sizes, int n_in,
                              void* d_out, int out_size) {
    const float* x      = (const float*)d_in[0];
    const float* gns    = (const float*)d_in[1];
    const float* gnb    = (const float*)d_in[2];
    const float* wq     = (const float*)d_in[3];
    const float* bq     = (const float*)d_in[4];
    const float* wk     = (const float*)d_in[5];
    const float* bk     = (const float*)d_in[6];
    const float* wv     = (const float*)d_in[7];
    const float* bv     = (const float*)d_in[8];
    const float* wproj  = (const float*)d_in[9];
    const float* bproj  = (const float*)d_in[10];
    const float* dq     = (const float*)d_in[11];
    const float* zq     = (const float*)d_in[12];
    const float* dk     = (const float*)d_in[13];
    const float* zk     = (const float*)d_in[14];
    const float* dv     = (const float*)d_in[15];
    const float* zv     = (const float*)d_in[16];
    const float* dw     = (const float*)d_in[17];
    const float* zw     = (const float*)d_in[18];
    float* out = (float*)d_out;

    gn_kernel<<<NB * 32, 256>>>(x, gns, gnb);
    wsplit_kernel<<<256, 256>>>(wq, wk, wv, wproj);
    qkv_kernel<<<dim3(NHW / 128, NC / 128, NB * 3), 256>>>(
        bq, bk, bv, dq, zq, dk, zk, dv, zv);
    gemm1_kernel<<<dim3(NHW / 128, NHW / 128, NB), 256>>>(dq, dk);
    softmax_kernel<<<NB * NHW, 256>>>(dw, zw);
    gemm2_kernel<<<dim3(NHW / 128, NC / 128, NB), 256>>>(dv, dw);
    proj_kernel<<<dim3(NHW / 128, NC / 128, NB), 256>>>(x, bproj, out);
}

// round 8
// speedup vs baseline: 2.8864x; 1.1203x over previous
#include <cuda_runtime.h>
#include <cuda_bf16.h>
#include <cuda_fp16.h>
#include <cstdint>

#define NB 4
#define NC 256
#define NHW 4096
#define KT 32
#define SP 40    // padded smem row stride (bf16 elems) for conv kernels
#define KTG 64   // gemm1/gemm2 k-tile
#define SPG 72   // padded row stride for KTG tiles (144B, conflict-free)

// ---------------- scratch ----------------
__device__ __nv_bfloat16 g_hT_hi[NB*NHW*NC];
__device__ __nv_bfloat16 g_hT_lo[NB*NHW*NC];
__device__ __nv_bfloat16 g_w_hi[4*NC*NC];   // q,k,v,proj
__device__ __nv_bfloat16 g_w_lo[4*NC*NC];
__device__ __nv_bfloat16 g_q[NB*NHW*NC];    // quantized q codes [b][n][c]
__device__ __nv_bfloat16 g_k[NB*NHW*NC];    // quantized k codes [b][m][c]
__device__ __nv_bfloat16 g_v[NB*NC*NHW];    // quantized v codes [b][c][m]
__device__ __half        g_S[(size_t)NB*NHW*NHW];  // logits (f16)
__device__ __nv_bfloat16 g_a[(size_t)NB*NHW*NHW];  // quantized attn codes [b][n][m]
__device__ __nv_bfloat16 g_hoT_hi[NB*NHW*NC];
__device__ __nv_bfloat16 g_hoT_lo[NB*NHW*NC];

// ---------------- helpers ----------------
__device__ __forceinline__ void mma16816(float d[4], const uint32_t a[4], const uint32_t b[2]) {
    asm volatile(
        "mma.sync.aligned.m16n8k16.row.col.f32.bf16.bf16.f32 "
        "{%0,%1,%2,%3},{%4,%5,%6,%7},{%8,%9},{%0,%1,%2,%3};\n"
        : "+f"(d[0]), "+f"(d[1]), "+f"(d[2]), "+f"(d[3])
        : "r"(a[0]), "r"(a[1]), "r"(a[2]), "r"(a[3]), "r"(b[0]), "r"(b[1]));
}
__device__ __forceinline__ void ldsm4(uint32_t r[4], const void* p) {
    uint32_t a = (uint32_t)__cvta_generic_to_shared(p);
    asm volatile("ldmatrix.sync.aligned.m8n8.x4.shared.b16 {%0,%1,%2,%3},[%4];\n"
        : "=r"(r[0]), "=r"(r[1]), "=r"(r[2]), "=r"(r[3]) : "r"(a));
}
__device__ __forceinline__ void cp16(void* s, const void* g) {
    uint32_t sa = (uint32_t)__cvta_generic_to_shared(s);
    asm volatile("cp.async.cg.shared.global [%0],[%1],16;\n" :: "r"(sa), "l"(g));
}
#define CP_COMMIT() asm volatile("cp.async.commit_group;\n")
#define CP_WAIT0()  asm volatile("cp.async.wait_group 0;\n")
#define CP_WAIT1()  asm volatile("cp.async.wait_group 1;\n")

__device__ __forceinline__ float fq_code(float v, float dinv, float zp) {
    float q = rintf(v * dinv) + zp;
    q = fminf(fmaxf(q, 0.0f), 255.0f);
    return q - zp;
}

// ---------------- 1) GroupNorm -> hT hi/lo [b][n][c] ----------------
__global__ void __launch_bounds__(256) gn_kernel(const float* __restrict__ x,
                                                 const float* __restrict__ gam,
                                                 const float* __restrict__ bet) {
    int b = blockIdx.x >> 5, gr = blockIdx.x & 31;
    const float* xp = x + ((size_t)(b * NC) + gr * 8) * NHW;
    int tid = threadIdx.x;
    const int Nf4 = 8 * NHW / 4;
    const float4* x4 = (const float4*)xp;
    float s = 0.f, ss = 0.f;
    for (int i = tid; i < Nf4; i += 256) {
        float4 v = x4[i];
        s  += v.x + v.y + v.z + v.w;
        ss += v.x * v.x + v.y * v.y + v.z * v.z + v.w * v.w;
    }
    __shared__ float rs[8], rss[8], s_sc[8], s_sh[8];
    #pragma unroll
    for (int o = 16; o; o >>= 1) {
        s  += __shfl_down_sync(0xffffffffu, s, o);
        ss += __shfl_down_sync(0xffffffffu, ss, o);
    }
    if ((tid & 31) == 0) { rs[tid >> 5] = s; rss[tid >> 5] = ss; }
    __syncthreads();
    float ts = 0.f, tss = 0.f;
    #pragma unroll
    for (int k = 0; k < 8; k++) { ts += rs[k]; tss += rss[k]; }
    const float inv = 1.0f / (float)(8 * NHW);
    float mu = ts * inv;
    float var = tss * inv - mu * mu;
    float rstd = 1.0f / sqrtf(var + 1e-6f);
    if (tid < 8) {
        float gm = gam[gr * 8 + tid];
        s_sc[tid] = gm * rstd;
        s_sh[tid] = bet[gr * 8 + tid] - mu * gm * rstd;
    }
    __syncthreads();
    __nv_bfloat16* Hh = g_hT_hi + (size_t)b * NHW * NC + gr * 8;
    __nv_bfloat16* Hl = g_hT_lo + (size_t)b * NHW * NC + gr * 8;
    for (int n = tid; n < NHW; n += 256) {
        union { __nv_bfloat16 h[8]; uint4 u; } ph, pl;
        #pragma unroll
        for (int c = 0; c < 8; c++) {
            float v = xp[(size_t)c * NHW + n] * s_sc[c] + s_sh[c];
            __nv_bfloat16 hi = __float2bfloat16(v);
            ph.h[c] = hi;
            pl.h[c] = __float2bfloat16(v - __bfloat162float(hi));
        }
        *(uint4*)&Hh[(size_t)n * NC] = ph.u;
        *(uint4*)&Hl[(size_t)n * NC] = pl.u;
    }
}

// ---------------- 2) weight split ----------------
__global__ void __launch_bounds__(256) wsplit_kernel(const float* __restrict__ wq,
                                                     const float* __restrict__ wk,
                                                     const float* __restrict__ wv,
                                                     const float* __restrict__ wp) {
    int idx = blockIdx.x * 256 + threadIdx.x;
    const float* ws[4] = {wq, wk, wv, wp};
    #pragma unroll
    for (int m = 0; m < 4; m++) {
        float v = ws[m][idx];
        __nv_bfloat16 hi = __float2bfloat16(v);
        g_w_hi[m * NC * NC + idx] = hi;
        g_w_lo[m * NC * NC + idx] = __float2bfloat16(v - __bfloat162float(hi));
    }
}

// ---------------- 3) QKV: split-bf16 mma conv + quantize (ldmatrix) ----------------
__global__ void __launch_bounds__(256) qkv_kernel(
    const float* __restrict__ bq, const float* __restrict__ bk, const float* __restrict__ bv,
    const float* __restrict__ dqp, const float* __restrict__ zqp,
    const float* __restrict__ dkp, const float* __restrict__ zkp,
    const float* __restrict__ dvp, const float* __restrict__ zvp) {
    int z = blockIdx.z;
    int b = z / 3, which = z - b * 3;
    const __nv_bfloat16* Wh = g_w_hi + which * NC * NC;
    const __nv_bfloat16* Wl = g_w_lo + which * NC * NC;
    const float* bias;
    float d, zp;
    if (which == 0)      { bias = bq; d = dqp[0]; zp = zqp[0]; }
    else if (which == 1) { bias = bk; d = dkp[0]; zp = zkp[0]; }
    else                 { bias = bv; d = dvp[0]; zp = zvp[0]; }
    int n0 = blockIdx.x * 128, o0 = blockIdx.y * 128;
    const __nv_bfloat16* Ahg = g_hT_hi + (size_t)b * NHW * NC;
    const __nv_bfloat16* Alg = g_hT_lo + (size_t)b * NHW * NC;

    __shared__ union SmU {
        struct { __nv_bfloat16 Ah[128][SP], Al[128][SP], Bh[128][SP], Bl[128][SP]; } m;
        __nv_bfloat16 tb[128][136];
    } sm;

    int tid = threadIdx.x, warp = tid >> 5, lane = tid & 31;
    int g = lane >> 2, ti = lane & 3, wr = warp & 1, wc = warp >> 1;
    int la  = lane & 15;
    int kA  = ((lane >> 4) & 1) * 8;
    int lb  = (lane & 7) + ((lane >> 4) & 1) * 8;
    int kB  = ((lane >> 3) & 1) * 8;
    float acc[4][4][4] = {};

    for (int k0 = 0; k0 < NC; k0 += KT) {
        #pragma unroll
        for (int u = 0; u < 2; u++) {
            int c = tid + u * 256; int r = c >> 2, q = (c & 3) * 8;
            cp16(&sm.m.Ah[r][q], &Ahg[(size_t)(n0 + r) * NC + k0 + q]);
            cp16(&sm.m.Al[r][q], &Alg[(size_t)(n0 + r) * NC + k0 + q]);
            cp16(&sm.m.Bh[r][q], &Wh[(o0 + r) * NC + k0 + q]);
            cp16(&sm.m.Bl[r][q], &Wl[(o0 + r) * NC + k0 + q]);
        }
        CP_COMMIT(); CP_WAIT0();
        __syncthreads();
        #pragma unroll
        for (int kk = 0; kk < KT; kk += 16) {
            uint32_t ah[4][4], al[4][4], bh[2][4], bl[2][4];
            #pragma unroll
            for (int mi = 0; mi < 4; mi++) {
                int r = wr * 64 + mi * 16 + la;
                ldsm4(ah[mi], &sm.m.Ah[r][kk + kA]);
                ldsm4(al[mi], &sm.m.Al[r][kk + kA]);
            }
            #pragma unroll
            for (int nj = 0; nj < 2; nj++) {
                int c = wc * 32 + nj * 16 + lb;
                ldsm4(bh[nj], &sm.m.Bh[c][kk + kB]);
                ldsm4(bl[nj], &sm.m.Bl[c][kk + kB]);
            }
            #pragma unroll
            for (int mi = 0; mi < 4; mi++)
                #pragma unroll
                for (int ni = 0; ni < 4; ni++) {
                    mma16816(acc[mi][ni], ah[mi], &bh[ni >> 1][(ni & 1) * 2]);
                    mma16816(acc[mi][ni], ah[mi], &bl[ni >> 1][(ni & 1) * 2]);
                    mma16816(acc[mi][ni], al[mi], &bh[ni >> 1][(ni & 1) * 2]);
                }
        }
        __syncthreads();
    }

    float dinv = 1.0f / d;
    if (which < 2) {
        __nv_bfloat16* Out = (which == 0 ? g_q : g_k) + (size_t)b * NHW * NC;
        #pragma unroll
        for (int mi = 0; mi < 4; mi++) {
            int n = n0 + wr * 64 + mi * 16 + g;
            #pragma unroll
            for (int ni = 0; ni < 4; ni++) {
                int o = o0 + wc * 32 + ni * 8 + 2 * ti;
                float b0 = bias[o], b1 = bias[o + 1];
                union { __nv_bfloat16 h[2]; uint32_t u; } p0, p1;
                p0.h[0] = __float2bfloat16(fq_code(acc[mi][ni][0] + b0, dinv, zp));
                p0.h[1] = __float2bfloat16(fq_code(acc[mi][ni][1] + b1, dinv, zp));
                p1.h[0] = __float2bfloat16(fq_code(acc[mi][ni][2] + b0, dinv, zp));
                p1.h[1] = __float2bfloat16(fq_code(acc[mi][ni][3] + b1, dinv, zp));
                *(uint32_t*)&Out[(size_t)n * NC + o]       = p0.u;
                *(uint32_t*)&Out[(size_t)(n + 8) * NC + o] = p1.u;
            }
        }
    } else {
        #pragma unroll
        for (int mi = 0; mi < 4; mi++) {
            int nl = wr * 64 + mi * 16 + g;
            #pragma unroll
            for (int ni = 0; ni < 4; ni++) {
                int ol = wc * 32 + ni * 8 + 2 * ti;
                float b0 = bias[o0 + ol], b1 = bias[o0 + ol + 1];
                sm.tb[ol    ][nl    ] = __float2bfloat16(fq_code(acc[mi][ni][0] + b0, dinv, zp));
                sm.tb[ol + 1][nl    ] = __float2bfloat16(fq_code(acc[mi][ni][1] + b1, dinv, zp));
                sm.tb[ol    ][nl + 8] = __float2bfloat16(fq_code(acc[mi][ni][2] + b0, dinv, zp));
                sm.tb[ol + 1][nl + 8] = __float2bfloat16(fq_code(acc[mi][ni][3] + b1, dinv, zp));
            }
        }
        __syncthreads();
        int r = tid >> 1, half = (tid & 1) * 64;
        #pragma unroll
        for (int j = 0; j < 64; j += 8)
            *(uint4*)&g_v[((size_t)b * NC + o0 + r) * NHW + n0 + half + j] =
                *(uint4*)&sm.tb[r][half + j];
    }
}

// ---------------- 4) gemm1: S = q . k^T (bf16 mma, KTG=64, f16 out) ----------------
__global__ void __launch_bounds__(256) gemm1_kernel(const float* __restrict__ dqp,
                                                    const float* __restrict__ dkp) {
    extern __shared__ __nv_bfloat16 ds[];
    __nv_bfloat16 (*As)[128][SPG] = (__nv_bfloat16 (*)[128][SPG])ds;
    __nv_bfloat16 (*Bs)[128][SPG] = (__nv_bfloat16 (*)[128][SPG])(ds + 2 * 128 * SPG);

    int b = blockIdx.z, m0 = blockIdx.x * 128, n0 = blockIdx.y * 128;
    const __nv_bfloat16* A  = g_q + (size_t)b * NHW * NC;
    const __nv_bfloat16* Bm = g_k + (size_t)b * NHW * NC;
    int tid = threadIdx.x, warp = tid >> 5, lane = tid & 31;
    int g = lane >> 2, ti = lane & 3, wr = warp & 1, wc = warp >> 1;
    int la  = lane & 15;
    int kA  = ((lane >> 4) & 1) * 8;
    int lb  = (lane & 7) + ((lane >> 4) & 1) * 8;
    int kB  = ((lane >> 3) & 1) * 8;
    float acc[4][4][4] = {};
    #pragma unroll
    for (int u = 0; u < 4; u++) {
        int c = tid + u * 256; int r = c >> 3, q = (c & 7) * 8;
        cp16(&As[0][r][q], &A [(size_t)(n0 + r) * NC + q]);
        cp16(&Bs[0][r][q], &Bm[(size_t)(m0 + r) * NC + q]);
    }
    CP_COMMIT();
    const int T = NC / KTG;   // 4
    for (int t = 0; t < T; t++) {
        if (t + 1 < T) {
            int k0 = (t + 1) * KTG, bi = (t + 1) & 1;
            #pragma unroll
            for (int u = 0; u < 4; u++) {
                int c = tid + u * 256; int r = c >> 3, q = (c & 7) * 8;
                cp16(&As[bi][r][q], &A [(size_t)(n0 + r) * NC + k0 + q]);
                cp16(&Bs[bi][r][q], &Bm[(size_t)(m0 + r) * NC + k0 + q]);
            }
            CP_COMMIT(); CP_WAIT1();
        } else CP_WAIT0();
        __syncthreads();
        int bi = t & 1;
        #pragma unroll
        for (int kk = 0; kk < KTG; kk += 16) {
            uint32_t af[4][4], bf[2][4];
            #pragma unroll
            for (int mi = 0; mi < 4; mi++)
                ldsm4(af[mi], &As[bi][wr * 64 + mi * 16 + la][kk + kA]);
            #pragma unroll
            for (int nj = 0; nj < 2; nj++)
                ldsm4(bf[nj], &Bs[bi][wc * 32 + nj * 16 + lb][kk + kB]);
            #pragma unroll
            for (int mi = 0; mi < 4; mi++)
                #pragma unroll
                for (int ni = 0; ni < 4; ni++)
                    mma16816(acc[mi][ni], af[mi], &bf[ni >> 1][(ni & 1) * 2]);
        }
        __syncthreads();
    }
    float sc = dqp[0] * dkp[0] * 0.0625f;
    __half* Sp = g_S + (size_t)b * NHW * NHW;
    #pragma unroll
    for (int mi = 0; mi < 4; mi++) {
        int n = n0 + wr * 64 + mi * 16 + g;
        #pragma unroll
        for (int ni = 0; ni < 4; ni++) {
            int m = m0 + wc * 32 + ni * 8 + 2 * ti;
            *(__half2*)&Sp[(size_t)n * NHW + m] =
                __floats2half2_rn(acc[mi][ni][0] * sc, acc[mi][ni][1] * sc);
            *(__half2*)&Sp[(size_t)(n + 8) * NHW + m] =
                __floats2half2_rn(acc[mi][ni][2] * sc, acc[mi][ni][3] * sc);
        }
    }
}

// ---------------- 5) softmax + 8-bit quantize (f16 in, bf16 codes out) ----------------
__global__ void __launch_bounds__(256) softmax_kernel(const float* __restrict__ dwp,
                                                      const float* __restrict__ zwp) {
    size_t row = blockIdx.x;
    const __half* s = g_S + row * NHW;
    __nv_bfloat16* a = g_a + row * NHW;
    int tid = threadIdx.x;
    float v[16];
    #pragma unroll
    for (int j = 0; j < 2; j++) {
        uint4 t = *(const uint4*)&s[(j * 256 + tid) * 8];
        const __half2* hp = (const __half2*)&t;
        #pragma unroll
        for (int l = 0; l < 4; l++) {
            float2 f = __half22float2(hp[l]);
            v[j * 8 + 2 * l]     = f.x;
            v[j * 8 + 2 * l + 1] = f.y;
        }
    }
    float mx = -3.4e38f;
    #pragma unroll
    for (int i = 0; i < 16; i++) mx = fmaxf(mx, v[i]);
    __shared__ float red[8];
    #pragma unroll
    for (int o = 16; o; o >>= 1) mx = fmaxf(mx, __shfl_xor_sync(0xffffffffu, mx, o));
    if ((tid & 31) == 0) red[tid >> 5] = mx;
    __syncthreads();
    mx = red[0];
    #pragma unroll
    for (int k = 1; k < 8; k++) mx = fmaxf(mx, red[k]);
    __syncthreads();
    float sum = 0.f;
    #pragma unroll
    for (int i = 0; i < 16; i++) { v[i] = __expf(v[i] - mx); sum += v[i]; }
    #pragma unroll
    for (int o = 16; o; o >>= 1) sum += __shfl_xor_sync(0xffffffffu, sum, o);
    if ((tid & 31) == 0) red[tid >> 5] = sum;
    __syncthreads();
    sum = 0.f;
    #pragma unroll
    for (int k = 0; k < 8; k++) sum += red[k];
    float rinv = 1.0f / sum;
    float dinv = 1.0f / dwp[0], zw = zwp[0];
    #pragma unroll
    for (int j = 0; j < 2; j++) {
        union { __nv_bfloat16 h[8]; uint4 u; } pk;
        #pragma unroll
        for (int l = 0; l < 8; l++)
            pk.h[l] = __float2bfloat16(fq_code(v[j * 8 + l] * rinv, dinv, zw));
        *(uint4*)&a[(j * 256 + tid) * 8] = pk.u;
    }
}

// ---------------- 6) gemm2: hoT = a . v^T, emit split hi/lo (KTG=64) ----------------
__global__ void __launch_bounds__(256) gemm2_kernel(const float* __restrict__ dvp,
                                                    const float* __restrict__ dwp) {
    extern __shared__ __nv_bfloat16 ds[];
    __nv_bfloat16 (*As)[128][SPG] = (__nv_bfloat16 (*)[128][SPG])ds;
    __nv_bfloat16 (*Bs)[128][SPG] = (__nv_bfloat16 (*)[128][SPG])(ds + 2 * 128 * SPG);

    int b = blockIdx.z, n0 = blockIdx.x * 128, c0 = blockIdx.y * 128;
    const __nv_bfloat16* A  = g_a + (size_t)b * NHW * NHW;   // [n][m]
    const __nv_bfloat16* Bm = g_v + (size_t)b * NC * NHW;    // [c][m]
    int tid = threadIdx.x, warp = tid >> 5, lane = tid & 31;
    int g = lane >> 2, ti = lane & 3, wr = warp & 1, wc = warp >> 1;
    int la  = lane & 15;
    int kA  = ((lane >> 4) & 1) * 8;
    int lb  = (lane & 7) + ((lane >> 4) & 1) * 8;
    int kB  = ((lane >> 3) & 1) * 8;
    float acc[4][4][4] = {};
    #pragma unroll
    for (int u = 0; u < 4; u++) {
        int c = tid + u * 256; int r = c >> 3, q = (c & 7) * 8;
        cp16(&As[0][r][q], &A [(size_t)(n0 + r) * NHW + q]);
        cp16(&Bs[0][r][q], &Bm[(size_t)(c0 + r) * NHW + q]);
    }
    CP_COMMIT();
    const int T = NHW / KTG;  // 64
    for (int t = 0; t < T; t++) {
        if (t + 1 < T) {
            int k0 = (t + 1) * KTG, bi = (t + 1) & 1;
            #pragma unroll
            for (int u = 0; u < 4; u++) {
                int c = tid + u * 256; int r = c >> 3, q = (c & 7) * 8;
                cp16(&As[bi][r][q], &A [(size_t)(n0 + r) * NHW + k0 + q]);
                cp16(&Bs[bi][r][q], &Bm[(size_t)(c0 + r) * NHW + k0 + q]);
            }
            CP_COMMIT(); CP_WAIT1();
        } else CP_WAIT0();
        __syncthreads();
        int bi = t & 1;
        #pragma unroll
        for (int kk = 0; kk < KTG; kk += 16) {
            uint32_t af[4][4], bf[2][4];
            #pragma unroll
            for (int mi = 0; mi < 4; mi++)
                ldsm4(af[mi], &As[bi][wr * 64 + mi * 16 + la][kk + kA]);
            #pragma unroll
            for (int nj = 0; nj < 2; nj++)
                ldsm4(bf[nj], &Bs[bi][wc * 32 + nj * 16 + lb][kk + kB]);
            #pragma unroll
            for (int mi = 0; mi < 4; mi++)
                #pragma unroll
                for (int ni = 0; ni < 4; ni++)
                    mma16816(acc[mi][ni], af[mi], &bf[ni >> 1][(ni & 1) * 2]);
        }
        __syncthreads();
    }
    float sc = dvp[0] * dwp[0];
    __nv_bfloat16* Oh = g_hoT_hi + (size_t)b * NHW * NC;
    __nv_bfloat16* Ol = g_hoT_lo + (size_t)b * NHW * NC;
    #pragma unroll
    for (int mi = 0; mi < 4; mi++) {
        int n = n0 + wr * 64 + mi * 16 + g;
        #pragma unroll
        for (int ni = 0; ni < 4; ni++) {
            int c = c0 + wc * 32 + ni * 8 + 2 * ti;
            #pragma unroll
            for (int half = 0; half < 2; half++) {
                float v0 = acc[mi][ni][2 * half] * sc;
                float v1 = acc[mi][ni][2 * half + 1] * sc;
                __nv_bfloat16 h0 = __float2bfloat16(v0);
                __nv_bfloat16 h1 = __float2bfloat16(v1);
                union { __nv_bfloat16 h[2]; uint32_t u; } ph, pl;
                ph.h[0] = h0; ph.h[1] = h1;
                pl.h[0] = __float2bfloat16(v0 - __bfloat162float(h0));
                pl.h[1] = __float2bfloat16(v1 - __bfloat162float(h1));
                size_t off = (size_t)(n + 8 * half) * NC + c;
                *(uint32_t*)&Oh[off] = ph.u;
                *(uint32_t*)&Ol[off] = pl.u;
            }
        }
    }
}

// ---------------- 7) proj: split-bf16 mma + bias + residual (ldmatrix) ----------------
__global__ void __launch_bounds__(256) proj_kernel(const float* __restrict__ x,
                                                   const float* __restrict__ bias,
                                                   float* __restrict__ out) {
    int b = blockIdx.z;
    int n0 = blockIdx.x * 128, o0 = blockIdx.y * 128;
    const __nv_bfloat16* Wh = g_w_hi + 3 * NC * NC;
    const __nv_bfloat16* Wl = g_w_lo + 3 * NC * NC;
    const __nv_bfloat16* Ahg = g_hoT_hi + (size_t)b * NHW * NC;
    const __nv_bfloat16* Alg = g_hoT_lo + (size_t)b * NHW * NC;

    __shared__ union SmU {
        struct { __nv_bfloat16 Ah[128][SP], Al[128][SP], Bh[128][SP], Bl[128][SP]; } m;
        float tf[64][132];
    } sm;

    int tid = threadIdx.x, warp = tid >> 5, lane = tid & 31;
    int g = lane >> 2, ti = lane & 3, wr = warp & 1, wc = warp >> 1;
    int la  = lane & 15;
    int kA  = ((lane >> 4) & 1) * 8;
    int lb  = (lane & 7) + ((lane >> 4) & 1) * 8;
    int kB  = ((lane >> 3) & 1) * 8;
    float acc[4][4][4] = {};

    for (int k0 = 0; k0 < NC; k0 += KT) {
        #pragma unroll
        for (int u = 0; u < 2; u++) {
            int c = tid + u * 256; int r = c >> 2, q = (c & 3) * 8;
            cp16(&sm.m.Ah[r][q], &Ahg[(size_t)(n0 + r) * NC + k0 + q]);
            cp16(&sm.m.Al[r][q], &Alg[(size_t)(n0 + r) * NC + k0 + q]);
            cp16(&sm.m.Bh[r][q], &Wh[(o0 + r) * NC + k0 + q]);
            cp16(&sm.m.Bl[r][q], &Wl[(o0 + r) * NC + k0 + q]);
        }
        CP_COMMIT(); CP_WAIT0();
        __syncthreads();
        #pragma unroll
        for (int kk = 0; kk < KT; kk += 16) {
            uint32_t ah[4][4], al[4][4], bh[2][4], bl[2][4];
            #pragma unroll
            for (int mi = 0; mi < 4; mi++) {
                int r = wr * 64 + mi * 16 + la;
                ldsm4(ah[mi], &sm.m.Ah[r][kk + kA]);
                ldsm4(al[mi], &sm.m.Al[r][kk + kA]);
            }
            #pragma unroll
            for (int nj = 0; nj < 2; nj++) {
                int c = wc * 32 + nj * 16 + lb;
                ldsm4(bh[nj], &sm.m.Bh[c][kk + kB]);
                ldsm4(bl[nj], &sm.m.Bl[c][kk + kB]);
            }
            #pragma unroll
            for (int mi = 0; mi < 4; mi++)
                #pragma unroll
                for (int ni = 0; ni < 4; ni++) {
                    mma16816(acc[mi][ni], ah[mi], &bh[ni >> 1][(ni & 1) * 2]);
                    mma16816(acc[mi][ni], ah[mi], &bl[ni >> 1][(ni & 1) * 2]);
                    mma16816(acc[mi][ni], al[mi], &bh[ni >> 1][(ni & 1) * 2]);
                }
        }
        __syncthreads();
    }

    #pragma unroll
    for (int hp = 0; hp < 2; hp++) {
        if ((wc >> 1) == hp) {
            #pragma unroll
            for (int mi = 0; mi < 4; mi++) {
                int nl = wr * 64 + mi * 16 + g;
                #pragma unroll
                for (int ni = 0; ni < 4; ni++) {
                    int ol = (wc & 1) * 32 + ni * 8 + 2 * ti;
                    sm.tf[ol    ][nl    ] = acc[mi][ni][0];
                    sm.tf[ol + 1][nl    ] = acc[mi][ni][1];
                    sm.tf[ol    ][nl + 8] = acc[mi][ni][2];
                    sm.tf[ol + 1][nl + 8] = acc[mi][ni][3];
                }
            }
        }
        __syncthreads();
        int r = tid >> 2, qn = (tid & 3) * 32;
        int o = o0 + hp * 64 + r;
        float bo = bias[o];
        size_t bse = ((size_t)b * NC + o) * NHW + n0 + qn;
        #pragma unroll
        for (int j = 0; j < 32; j += 4) {
            float4 xv = *(const float4*)&x[bse + j];
            float4 tv = *(const float4*)&sm.tf[r][qn + j];
            float4 rv;
            rv.x = xv.x + tv.x + bo; rv.y = xv.y + tv.y + bo;
            rv.z = xv.z + tv.z + bo; rv.w = xv.w + tv.w + bo;
            *(float4*)&out[bse + j] = rv;
        }
        __syncthreads();
    }
}

// ---------------- launch ----------------
extern "C" void kernel_launch(void* const* d_in, const int* in_sizes, int n_in,
                              void* d_out, int out_size) {
    const float* x      = (const float*)d_in[0];
    const float* gns    = (const float*)d_in[1];
    const float* gnb    = (const float*)d_in[2];
    const float* wq     = (const float*)d_in[3];
    const float* bq     = (const float*)d_in[4];
    const float* wk     = (const float*)d_in[5];
    const float* bk     = (const float*)d_in[6];
    const float* wv     = (const float*)d_in[7];
    const float* bv     = (const float*)d_in[8];
    const float* wproj  = (const float*)d_in[9];
    const float* bproj  = (const float*)d_in[10];
    const float* dq     = (const float*)d_in[11];
    const float* zq     = (const float*)d_in[12];
    const float* dk     = (const float*)d_in[13];
    const float* zk     = (const float*)d_in[14];
    const float* dv     = (const float*)d_in[15];
    const float* zv     = (const float*)d_in[16];
    const float* dw     = (const float*)d_in[17];
    const float* zw     = (const float*)d_in[18];
    float* out = (float*)d_out;

    const int GSMEM = 4 * 128 * SPG * 2;   // 73728 B
    cudaFuncSetAttribute(gemm1_kernel, cudaFuncAttributeMaxDynamicSharedMemorySize, GSMEM);
    cudaFuncSetAttribute(gemm2_kernel, cudaFuncAttributeMaxDynamicSharedMemorySize, GSMEM);

    gn_kernel<<<NB * 32, 256>>>(x, gns, gnb);
    wsplit_kernel<<<256, 256>>>(wq, wk, wv, wproj);
    qkv_kernel<<<dim3(NHW / 128, NC / 128, NB * 3), 256>>>(
        bq, bk, bv, dq, zq, dk, zk, dv, zv);
    gemm1_kernel<<<dim3(NHW / 128, NHW / 128, NB), 256, GSMEM>>>(dq, dk);
    softmax_kernel<<<NB * NHW, 256>>>(dw, zw);
    gemm2_kernel<<<dim3(NHW / 128, NC / 128, NB), 256, GSMEM>>>(dv, dw);
    proj_kernel<<<dim3(NHW / 128, NC / 128, NB), 256>>>(x, bproj, out);
}